// round 16
// baseline (speedup 1.0000x reference)
#include <cuda_runtime.h>
#include <cuda_fp16.h>
#include <cstdint>

// ---------------- problem dims ----------------
#define TOKENS 8192
#define HIDDEN 2048
#define INTER  5632

// ---------------- scratch (__device__ globals; allocation-free) ----------------
__device__ __half g_wg[(size_t)HIDDEN * INTER];   // gate W [H, I] fp16
__device__ __half g_wu[(size_t)HIDDEN * INTER];   // up   W [H, I] fp16
__device__ __half g_wd[(size_t)INTER * HIDDEN];   // down W [I, H] fp16
__device__ __half g_x [(size_t)TOKENS * HIDDEN];  // x fp16 [T, H]
__device__ __half g_h [(size_t)TOKENS * INTER];   // h = silu(g)*u fp16 [T, I]

// ---------------- helpers ----------------
__device__ __forceinline__ uint32_t smem_u32(const void* p) {
    return (uint32_t)__cvta_generic_to_shared(p);
}
__device__ __forceinline__ void cp_async16(uint32_t saddr, const void* gptr) {
    asm volatile("cp.async.cg.shared.global [%0], [%1], 16;\n" :: "r"(saddr), "l"(gptr));
}
// fp16-accumulate HMMA: d(f16x4) += a(f16) @ b(f16)
__device__ __forceinline__ void mma_f16acc(uint32_t& d0, uint32_t& d1,
                                           const uint32_t a[4], const uint32_t b[2]) {
    asm volatile(
        "mma.sync.aligned.m16n8k16.row.col.f16.f16.f16.f16 "
        "{%0,%1}, {%2,%3,%4,%5}, {%6,%7}, {%0,%1};"
        : "+r"(d0), "+r"(d1)
        : "r"(a[0]), "r"(a[1]), "r"(a[2]), "r"(a[3]), "r"(b[0]), "r"(b[1]));
}
__device__ __forceinline__ void flush_acc(uint32_t& h0, uint32_t& h1, float* c) {
    float2 v0 = __half22float2(*reinterpret_cast<__half2*>(&h0));
    float2 v1 = __half22float2(*reinterpret_cast<__half2*>(&h1));
    c[0] += v0.x; c[1] += v0.y; c[2] += v1.x; c[3] += v1.y;
    h0 = 0u; h1 = 0u;
}

// ---------------- fused prep: x convert + 3 dequants (R13, proven) ---------
#define CONV_BLKS 4096
#define CONV_STRIDE (CONV_BLKS * 256)
#define DQ8_BLKS  704
#define PREP_BLKS (CONV_BLKS + 3 * DQ8_BLKS)

__device__ __forceinline__ void dequant_block8(const int* __restrict__ qw,
                                               const int* __restrict__ qz,
                                               const float* __restrict__ sc,
                                               __half* __restrict__ w,
                                               int idx, int out_dim) {
    const int outp = out_dim >> 3;
    const int kp = idx / outp;
    const int nb = idx - kp * outp;
    const int n0 = nb << 3;
    const int k0 = kp << 3;
    const int grp = k0 >> 7;

    const uint4* qptr = reinterpret_cast<const uint4*>(qw + (size_t)kp * out_dim + n0);
    uint4 qa = qptr[0], qb = qptr[1];
    unsigned qv[8] = {qa.x, qa.y, qa.z, qa.w, qb.x, qb.y, qb.z, qb.w};

    unsigned zw = (unsigned)qz[grp * outp + nb];
    const float4* sptr = reinterpret_cast<const float4*>(sc + (size_t)grp * out_dim + n0);
    float4 s0 = sptr[0], s1 = sptr[1];
    float scales[8] = {s0.x, s0.y, s0.z, s0.w, s1.x, s1.y, s1.z, s1.w};

    float zb[8];
    #pragma unroll
    for (int j = 0; j < 8; ++j)
        zb[j] = (float)(int)(((zw >> (j * 4)) & 0xF) + 1);

    #pragma unroll
    for (int i = 0; i < 8; ++i) {
        alignas(16) __half hv[8];
        #pragma unroll
        for (int j = 0; j < 8; ++j) {
            int q = (int)((qv[j] >> (i * 4)) & 0xF);
            hv[j] = __float2half_rn(((float)q - zb[j]) * scales[j]);
        }
        *reinterpret_cast<uint4*>(&w[(size_t)(k0 + i) * out_dim + n0]) =
            *reinterpret_cast<const uint4*>(hv);
    }
}

__global__ void __launch_bounds__(256)
prep_kernel(const float4* __restrict__ x,
            const int* __restrict__ gq, const int* __restrict__ gz, const float* __restrict__ gs,
            const int* __restrict__ uq, const int* __restrict__ uz, const float* __restrict__ us,
            const int* __restrict__ dq, const int* __restrict__ dz, const float* __restrict__ ds,
            __half* __restrict__ wg, __half* __restrict__ wu, __half* __restrict__ wd,
            uint2* __restrict__ xh)
{
    const int b = blockIdx.x;
    if (b < CONV_BLKS) {
        int i = b * 256 + threadIdx.x;
        #pragma unroll
        for (int r = 0; r < 4; ++r) {
            float4 v = x[i + r * CONV_STRIDE];
            __half2 a = __floats2half2_rn(v.x, v.y);
            __half2 c = __floats2half2_rn(v.z, v.w);
            uint2 o;
            o.x = *reinterpret_cast<uint32_t*>(&a);
            o.y = *reinterpret_cast<uint32_t*>(&c);
            xh[i + r * CONV_STRIDE] = o;
        }
    } else if (b < CONV_BLKS + DQ8_BLKS) {
        int i = (b - CONV_BLKS) * 256 + threadIdx.x;
        dequant_block8(gq, gz, gs, wg, i, INTER);
    } else if (b < CONV_BLKS + 2 * DQ8_BLKS) {
        int i = (b - CONV_BLKS - DQ8_BLKS) * 256 + threadIdx.x;
        dequant_block8(uq, uz, us, wu, i, INTER);
    } else {
        int i = (b - CONV_BLKS - 2 * DQ8_BLKS) * 256 + threadIdx.x;
        dequant_block8(dq, dz, ds, wd, i, HIDDEN);
    }
}

// ---------------- GEMM tile geometry (occ-2 design) ----------------
#define BM 128
#define BN 64
#define BK 32
#define LDA 40                       // 32 + 8 pad halves
#define LDB 72                       // 64 + 8 pad halves
#define A_HALVES (BM * LDA)          // 5120
#define B_HALVES (BK * LDB)          // 2304

// ================= fused gate+up GEMM (occ 2, fp16-acc mma) ================
#define S_GU 4
#define GU_STAGE_HALVES (A_HALVES + 2 * B_HALVES)            // 9728
#define GU_SMEM_BYTES   (S_GU * GU_STAGE_HALVES * 2)         // 77824

__global__ void __launch_bounds__(256, 2)
gemm_gateup_kernel(const __half* __restrict__ A, const __half* __restrict__ Bg,
                   const __half* __restrict__ Bu, __half* __restrict__ H)
{
    extern __shared__ __half sm[];
    const int tid  = threadIdx.x;
    const int lane = tid & 31;
    const int warp = tid >> 5;
    const int warpRow = warp >> 1;   // 0..3 (32 rows each)
    const int warpCol = warp & 1;    // 0..1 (32 cols each)
    const int mBase = blockIdx.y * BM;
    const int nBase = blockIdx.x * BN;

    float accg[2][4][4] = {};
    float accu[2][4][4] = {};
    uint32_t hg[2][4][2] = {};       // fp16 partials (K=32 window)
    uint32_t hu[2][4][2] = {};

    auto loadTile = [&](int buf, int kt) {
        const int k0 = kt * BK;
        __half* stA = sm + buf * GU_STAGE_HALVES;
        __half* stG = stA + A_HALVES;
        __half* stU = stG + B_HALVES;
        #pragma unroll
        for (int rep = 0; rep < 2; ++rep) {
            int i = tid + rep * 256;
            int r = i >> 2, c = i & 3;
            cp_async16(smem_u32(&stA[r * LDA + c * 8]),
                       A + (size_t)(mBase + r) * HIDDEN + (k0 + c * 8));
        }
        {
            int r = tid >> 3, c = tid & 7;
            size_t g = (size_t)(k0 + r) * INTER + (nBase + c * 8);
            uint32_t so = (uint32_t)(r * LDB + c * 8);
            cp_async16(smem_u32(&stG[so]), Bg + g);
            cp_async16(smem_u32(&stU[so]), Bu + g);
        }
    };

    const int nT = HIDDEN / BK;   // 64
    #pragma unroll
    for (int s = 0; s < S_GU - 1; ++s) {
        loadTile(s, s);
        asm volatile("cp.async.commit_group;" ::: "memory");
    }

    for (int it = 0; it < nT; ++it) {
        asm volatile("cp.async.wait_group %0;" :: "n"(S_GU - 2) : "memory");
        __syncthreads();
        if (it + S_GU - 1 < nT) loadTile((it + S_GU - 1) % S_GU, it + S_GU - 1);
        asm volatile("cp.async.commit_group;" ::: "memory");

        const int buf = it % S_GU;
        const uint32_t aBase = smem_u32(sm + buf * GU_STAGE_HALVES);
        const uint32_t gBase = aBase + A_HALVES * 2;
        const uint32_t uBase = gBase + B_HALVES * 2;

        #pragma unroll
        for (int ks = 0; ks < 2; ++ks) {
            const int kk = ks * 16;
            uint32_t af[2][4];
            #pragma unroll
            for (int mi = 0; mi < 2; ++mi) {
                int row = warpRow * 32 + mi * 16 + (lane & 15);
                int col = kk + ((lane >> 4) << 3);
                uint32_t addr = aBase + (uint32_t)((row * LDA + col) * 2);
                asm volatile(
                    "ldmatrix.sync.aligned.m8n8.x4.shared.b16 {%0,%1,%2,%3}, [%4];"
                    : "=r"(af[mi][0]), "=r"(af[mi][1]), "=r"(af[mi][2]), "=r"(af[mi][3])
                    : "r"(addr));
            }
            // gate
            {
                uint32_t bf[4][2];
                #pragma unroll
                for (int nj = 0; nj < 2; ++nj) {
                    int row = kk + (lane & 15);
                    int col = warpCol * 32 + nj * 16 + ((lane >> 4) << 3);
                    uint32_t addr = gBase + (uint32_t)((row * LDB + col) * 2);
                    uint32_t r0, r1, r2, r3;
                    asm volatile(
                        "ldmatrix.sync.aligned.m8n8.x4.trans.shared.b16 {%0,%1,%2,%3}, [%4];"
                        : "=r"(r0), "=r"(r1), "=r"(r2), "=r"(r3) : "r"(addr));
                    bf[nj * 2][0] = r0; bf[nj * 2][1] = r1;
                    bf[nj * 2 + 1][0] = r2; bf[nj * 2 + 1][1] = r3;
                }
                #pragma unroll
                for (int mi = 0; mi < 2; ++mi)
                    #pragma unroll
                    for (int ni = 0; ni < 4; ++ni)
                        mma_f16acc(hg[mi][ni][0], hg[mi][ni][1], af[mi], bf[ni]);
            }
            // up
            {
                uint32_t bf[4][2];
                #pragma unroll
                for (int nj = 0; nj < 2; ++nj) {
                    int row = kk + (lane & 15);
                    int col = warpCol * 32 + nj * 16 + ((lane >> 4) << 3);
                    uint32_t addr = uBase + (uint32_t)((row * LDB + col) * 2);
                    uint32_t r0, r1, r2, r3;
                    asm volatile(
                        "ldmatrix.sync.aligned.m8n8.x4.trans.shared.b16 {%0,%1,%2,%3}, [%4];"
                        : "=r"(r0), "=r"(r1), "=r"(r2), "=r"(r3) : "r"(addr));
                    bf[nj * 2][0] = r0; bf[nj * 2][1] = r1;
                    bf[nj * 2 + 1][0] = r2; bf[nj * 2 + 1][1] = r3;
                }
                #pragma unroll
                for (int mi = 0; mi < 2; ++mi)
                    #pragma unroll
                    for (int ni = 0; ni < 4; ++ni)
                        mma_f16acc(hu[mi][ni][0], hu[mi][ni][1], af[mi], bf[ni]);
            }
        }
        // flush fp16 partials (K=32 window) into fp32 accumulators
        #pragma unroll
        for (int mi = 0; mi < 2; ++mi)
            #pragma unroll
            for (int ni = 0; ni < 4; ++ni) {
                flush_acc(hg[mi][ni][0], hg[mi][ni][1], accg[mi][ni]);
                flush_acc(hu[mi][ni][0], hu[mi][ni][1], accu[mi][ni]);
            }
    }

    // epilogue: h = silu(g) * u, fp16
    #pragma unroll
    for (int mi = 0; mi < 2; ++mi) {
        #pragma unroll
        for (int ni = 0; ni < 4; ++ni) {
            int row = mBase + warpRow * 32 + mi * 16 + (lane >> 2);
            int col = nBase + warpCol * 32 + ni * 8 + ((lane & 3) << 1);
            float g0 = accg[mi][ni][0], g1 = accg[mi][ni][1];
            float g2 = accg[mi][ni][2], g3 = accg[mi][ni][3];
            float s0 = g0 / (1.0f + __expf(-g0));
            float s1 = g1 / (1.0f + __expf(-g1));
            float s2 = g2 / (1.0f + __expf(-g2));
            float s3 = g3 / (1.0f + __expf(-g3));
            __half2 h01 = __floats2half2_rn(s0 * accu[mi][ni][0], s1 * accu[mi][ni][1]);
            __half2 h23 = __floats2half2_rn(s2 * accu[mi][ni][2], s3 * accu[mi][ni][3]);
            *reinterpret_cast<__half2*>(&H[(size_t)row * INTER + col]) = h01;
            *reinterpret_cast<__half2*>(&H[(size_t)(row + 8) * INTER + col]) = h23;
        }
    }
}

// ================= down GEMM (occ 2, fp16-acc mma) =========================
#define S_DN 4
#define DN_STAGE_HALVES (A_HALVES + B_HALVES)                // 7424
#define DN_SMEM_BYTES   (S_DN * DN_STAGE_HALVES * 2)         // 59392

__global__ void __launch_bounds__(256, 2)
gemm_down_kernel(const __half* __restrict__ A, const __half* __restrict__ B,
                 float* __restrict__ C)
{
    extern __shared__ __half sm[];
    const int tid  = threadIdx.x;
    const int lane = tid & 31;
    const int warp = tid >> 5;
    const int warpRow = warp >> 1;   // 0..3
    const int warpCol = warp & 1;    // 0..1
    const int mBase = blockIdx.y * BM;
    const int nBase = blockIdx.x * BN;

    float acc[2][4][4] = {};
    uint32_t hc[2][4][2] = {};

    auto loadTile = [&](int buf, int kt) {
        const int k0 = kt * BK;
        __half* stA = sm + buf * DN_STAGE_HALVES;
        __half* stB = stA + A_HALVES;
        #pragma unroll
        for (int rep = 0; rep < 2; ++rep) {
            int i = tid + rep * 256;
            int r = i >> 2, c = i & 3;
            cp_async16(smem_u32(&stA[r * LDA + c * 8]),
                       A + (size_t)(mBase + r) * INTER + (k0 + c * 8));
        }
        {
            int r = tid >> 3, c = tid & 7;
            cp_async16(smem_u32(&stB[r * LDB + c * 8]),
                       B + (size_t)(k0 + r) * HIDDEN + (nBase + c * 8));
        }
    };

    const int nT = INTER / BK;   // 176
    #pragma unroll
    for (int s = 0; s < S_DN - 1; ++s) {
        loadTile(s, s);
        asm volatile("cp.async.commit_group;" ::: "memory");
    }

    for (int it = 0; it < nT; ++it) {
        asm volatile("cp.async.wait_group %0;" :: "n"(S_DN - 2) : "memory");
        __syncthreads();
        if (it + S_DN - 1 < nT) loadTile((it + S_DN - 1) % S_DN, it + S_DN - 1);
        asm volatile("cp.async.commit_group;" ::: "memory");

        const int buf = it % S_DN;
        const uint32_t aBase = smem_u32(sm + buf * DN_STAGE_HALVES);
        const uint32_t bBase = aBase + A_HALVES * 2;

        #pragma unroll
        for (int ks = 0; ks < 2; ++ks) {
            const int kk = ks * 16;
            uint32_t af[2][4];
            #pragma unroll
            for (int mi = 0; mi < 2; ++mi) {
                int row = warpRow * 32 + mi * 16 + (lane & 15);
                int col = kk + ((lane >> 4) << 3);
                uint32_t addr = aBase + (uint32_t)((row * LDA + col) * 2);
                asm volatile(
                    "ldmatrix.sync.aligned.m8n8.x4.shared.b16 {%0,%1,%2,%3}, [%4];"
                    : "=r"(af[mi][0]), "=r"(af[mi][1]), "=r"(af[mi][2]), "=r"(af[mi][3])
                    : "r"(addr));
            }
            uint32_t bf[4][2];
            #pragma unroll
            for (int nj = 0; nj < 2; ++nj) {
                int row = kk + (lane & 15);
                int col = warpCol * 32 + nj * 16 + ((lane >> 4) << 3);
                uint32_t addr = bBase + (uint32_t)((row * LDB + col) * 2);
                uint32_t r0, r1, r2, r3;
                asm volatile(
                    "ldmatrix.sync.aligned.m8n8.x4.trans.shared.b16 {%0,%1,%2,%3}, [%4];"
                    : "=r"(r0), "=r"(r1), "=r"(r2), "=r"(r3) : "r"(addr));
                bf[nj * 2][0] = r0; bf[nj * 2][1] = r1;
                bf[nj * 2 + 1][0] = r2; bf[nj * 2 + 1][1] = r3;
            }
            #pragma unroll
            for (int mi = 0; mi < 2; ++mi)
                #pragma unroll
                for (int ni = 0; ni < 4; ++ni)
                    mma_f16acc(hc[mi][ni][0], hc[mi][ni][1], af[mi], bf[ni]);
        }
        #pragma unroll
        for (int mi = 0; mi < 2; ++mi)
            #pragma unroll
            for (int ni = 0; ni < 4; ++ni)
                flush_acc(hc[mi][ni][0], hc[mi][ni][1], acc[mi][ni]);
    }

    #pragma unroll
    for (int mi = 0; mi < 2; ++mi) {
        #pragma unroll
        for (int ni = 0; ni < 4; ++ni) {
            int row = mBase + warpRow * 32 + mi * 16 + (lane >> 2);
            int col = nBase + warpCol * 32 + ni * 8 + ((lane & 3) << 1);
            float2* p0 = reinterpret_cast<float2*>(&C[(size_t)row * HIDDEN + col]);
            float2* p1 = reinterpret_cast<float2*>(&C[(size_t)(row + 8) * HIDDEN + col]);
            *p0 = make_float2(acc[mi][ni][0], acc[mi][ni][1]);
            *p1 = make_float2(acc[mi][ni][2], acc[mi][ni][3]);
        }
    }
}

// ---------------- launcher ----------------
extern "C" void kernel_launch(void* const* d_in, const int* in_sizes, int n_in,
                              void* d_out, int out_size) {
    (void)in_sizes; (void)n_in; (void)out_size;
    const float* x  = (const float*)d_in[0];
    const int*   gq = (const int*)  d_in[1];
    const int*   gz = (const int*)  d_in[2];
    const float* gs = (const float*)d_in[3];
    const int*   uq = (const int*)  d_in[4];
    const int*   uz = (const int*)  d_in[5];
    const float* us = (const float*)d_in[6];
    const int*   dq = (const int*)  d_in[7];
    const int*   dz = (const int*)  d_in[8];
    const float* ds = (const float*)d_in[9];

    void *wg, *wu, *wd, *xh, *hh;
    cudaGetSymbolAddress(&wg, g_wg);
    cudaGetSymbolAddress(&wu, g_wu);
    cudaGetSymbolAddress(&wd, g_wd);
    cudaGetSymbolAddress(&xh, g_x);
    cudaGetSymbolAddress(&hh, g_h);

    cudaFuncSetAttribute(gemm_gateup_kernel,
                         cudaFuncAttributeMaxDynamicSharedMemorySize, GU_SMEM_BYTES);
    cudaFuncSetAttribute(gemm_down_kernel,
                         cudaFuncAttributeMaxDynamicSharedMemorySize, DN_SMEM_BYTES);

    // 1) fused prep: x->fp16 + all three dequants
    prep_kernel<<<PREP_BLKS, 256>>>(
        (const float4*)x,
        gq, gz, gs, uq, uz, us, dq, dz, ds,
        (__half*)wg, (__half*)wu, (__half*)wd, (uint2*)xh);

    // 2) fused gate+up GEMM -> h (fp16), occ 2, fp16-acc
    {
        dim3 grid(INTER / BN, TOKENS / BM);   // (88, 64)
        gemm_gateup_kernel<<<grid, 256, GU_SMEM_BYTES>>>(
            (const __half*)xh, (const __half*)wg, (const __half*)wu, (__half*)hh);
    }
    // 3) down GEMM -> d_out (fp32), occ 2, fp16-acc
    {
        dim3 grid(HIDDEN / BN, TOKENS / BM);  // (32, 64)
        gemm_down_kernel<<<grid, 256, DN_SMEM_BYTES>>>(
            (const __half*)hh, (const __half*)wd, (float*)d_out);
    }
}

// round 17
// speedup vs baseline: 1.1748x; 1.1748x over previous
#include <cuda_runtime.h>
#include <cuda_fp16.h>
#include <cstdint>

// ---------------- problem dims ----------------
#define TOKENS 8192
#define HIDDEN 2048
#define INTER  5632

// ---------------- scratch (__device__ globals; allocation-free) ----------------
__device__ __half g_wg[(size_t)HIDDEN * INTER];   // gate W [H, I] fp16
__device__ __half g_wu[(size_t)HIDDEN * INTER];   // up   W [H, I] fp16
__device__ __half g_wd[(size_t)INTER * HIDDEN];   // down W [I, H] fp16
__device__ __half g_x [(size_t)TOKENS * HIDDEN];  // x fp16 [T, H]
__device__ __half g_h [(size_t)TOKENS * INTER];   // h = silu(g)*u fp16 [T, I]

__device__ int g_hcnt[64];   // per 128-row block of h: #gate+up tiles done (of 88)

// ---------------- helpers ----------------
__device__ __forceinline__ uint32_t smem_u32(const void* p) {
    return (uint32_t)__cvta_generic_to_shared(p);
}
__device__ __forceinline__ void cp_async16(uint32_t saddr, const void* gptr) {
    asm volatile("cp.async.cg.shared.global [%0], [%1], 16;\n" :: "r"(saddr), "l"(gptr));
}

// ---------------- fused prep: x convert + 3 dequants + counter reset -------
#define CONV_BLKS 4096
#define CONV_STRIDE (CONV_BLKS * 256)
#define DQ8_BLKS  704
#define PREP_BLKS (CONV_BLKS + 3 * DQ8_BLKS)

__device__ __forceinline__ void dequant_block8(const int* __restrict__ qw,
                                               const int* __restrict__ qz,
                                               const float* __restrict__ sc,
                                               __half* __restrict__ w,
                                               int idx, int out_dim) {
    const int outp = out_dim >> 3;
    const int kp = idx / outp;
    const int nb = idx - kp * outp;
    const int n0 = nb << 3;
    const int k0 = kp << 3;
    const int grp = k0 >> 7;

    const uint4* qptr = reinterpret_cast<const uint4*>(qw + (size_t)kp * out_dim + n0);
    uint4 qa = qptr[0], qb = qptr[1];
    unsigned qv[8] = {qa.x, qa.y, qa.z, qa.w, qb.x, qb.y, qb.z, qb.w};

    unsigned zw = (unsigned)qz[grp * outp + nb];
    const float4* sptr = reinterpret_cast<const float4*>(sc + (size_t)grp * out_dim + n0);
    float4 s0 = sptr[0], s1 = sptr[1];
    float scales[8] = {s0.x, s0.y, s0.z, s0.w, s1.x, s1.y, s1.z, s1.w};

    float zb[8];
    #pragma unroll
    for (int j = 0; j < 8; ++j)
        zb[j] = (float)(int)(((zw >> (j * 4)) & 0xF) + 1);

    #pragma unroll
    for (int i = 0; i < 8; ++i) {
        alignas(16) __half hv[8];
        #pragma unroll
        for (int j = 0; j < 8; ++j) {
            int q = (int)((qv[j] >> (i * 4)) & 0xF);
            hv[j] = __float2half_rn(((float)q - zb[j]) * scales[j]);
        }
        *reinterpret_cast<uint4*>(&w[(size_t)(k0 + i) * out_dim + n0]) =
            *reinterpret_cast<const uint4*>(hv);
    }
}

__global__ void __launch_bounds__(256)
prep_kernel(const float4* __restrict__ x,
            const int* __restrict__ gq, const int* __restrict__ gz, const float* __restrict__ gs,
            const int* __restrict__ uq, const int* __restrict__ uz, const float* __restrict__ us,
            const int* __restrict__ dq, const int* __restrict__ dz, const float* __restrict__ ds,
            __half* __restrict__ wg, __half* __restrict__ wu, __half* __restrict__ wd,
            uint2* __restrict__ xh)
{
    const int b = blockIdx.x;
    if (b == 0 && threadIdx.x < 64) g_hcnt[threadIdx.x] = 0;
    if (b < CONV_BLKS) {
        int i = b * 256 + threadIdx.x;
        #pragma unroll
        for (int r = 0; r < 4; ++r) {
            float4 v = x[i + r * CONV_STRIDE];
            __half2 a = __floats2half2_rn(v.x, v.y);
            __half2 c = __floats2half2_rn(v.z, v.w);
            uint2 o;
            o.x = *reinterpret_cast<uint32_t*>(&a);
            o.y = *reinterpret_cast<uint32_t*>(&c);
            xh[i + r * CONV_STRIDE] = o;
        }
    } else if (b < CONV_BLKS + DQ8_BLKS) {
        int i = (b - CONV_BLKS) * 256 + threadIdx.x;
        dequant_block8(gq, gz, gs, wg, i, INTER);
    } else if (b < CONV_BLKS + 2 * DQ8_BLKS) {
        int i = (b - CONV_BLKS - DQ8_BLKS) * 256 + threadIdx.x;
        dequant_block8(uq, uz, us, wu, i, INTER);
    } else {
        int i = (b - CONV_BLKS - 2 * DQ8_BLKS) * 256 + threadIdx.x;
        dequant_block8(dq, dz, ds, wd, i, HIDDEN);
    }
}

// ---------------- GEMM tile geometry (occ-2 design, R15) ----------------
#define BM 128
#define BN 64
#define BK 32
#define LDA 40                       // 32 + 8 pad halves
#define LDB 72                       // 64 + 8 pad halves
#define A_HALVES (BM * LDA)          // 5120
#define B_HALVES (BK * LDB)          // 2304

#define S_GU 4
#define GU_STAGE_HALVES (A_HALVES + 2 * B_HALVES)            // 9728
#define GU_SMEM_BYTES   (S_GU * GU_STAGE_HALVES * 2)         // 77824

#define S_DN 4
#define DN_STAGE_HALVES (A_HALVES + B_HALVES)                // 7424

#define GU_TILES 5632     // (INTER/BN)=88 x (TOKENS/BM)=64
#define DN_TILES 2048     // (HIDDEN/BN)=32 x (TOKENS/BM)=64
#define MERGED_BLKS (GU_TILES + DN_TILES)

// ================= gate+up tile (occ 2, fp32 acc) ==========================
__device__ void gateup_tile(__half* sm, int bx, int by,
                            const __half* __restrict__ A, const __half* __restrict__ Bg,
                            const __half* __restrict__ Bu, __half* __restrict__ H)
{
    const int tid  = threadIdx.x;
    const int lane = tid & 31;
    const int warp = tid >> 5;
    const int warpRow = warp >> 1;   // 0..3 (32 rows each)
    const int warpCol = warp & 1;    // 0..1 (32 cols each)
    const int mBase = by * BM;
    const int nBase = bx * BN;

    float accg[2][4][4] = {};
    float accu[2][4][4] = {};

    auto loadTile = [&](int buf, int kt) {
        const int k0 = kt * BK;
        __half* stA = sm + buf * GU_STAGE_HALVES;
        __half* stG = stA + A_HALVES;
        __half* stU = stG + B_HALVES;
        #pragma unroll
        for (int rep = 0; rep < 2; ++rep) {
            int i = tid + rep * 256;
            int r = i >> 2, c = i & 3;
            cp_async16(smem_u32(&stA[r * LDA + c * 8]),
                       A + (size_t)(mBase + r) * HIDDEN + (k0 + c * 8));
        }
        {
            int r = tid >> 3, c = tid & 7;
            size_t g = (size_t)(k0 + r) * INTER + (nBase + c * 8);
            uint32_t so = (uint32_t)(r * LDB + c * 8);
            cp_async16(smem_u32(&stG[so]), Bg + g);
            cp_async16(smem_u32(&stU[so]), Bu + g);
        }
    };

    const int nT = HIDDEN / BK;   // 64
    #pragma unroll
    for (int s = 0; s < S_GU - 1; ++s) {
        loadTile(s, s);
        asm volatile("cp.async.commit_group;" ::: "memory");
    }

    for (int it = 0; it < nT; ++it) {
        asm volatile("cp.async.wait_group %0;" :: "n"(S_GU - 2) : "memory");
        __syncthreads();
        if (it + S_GU - 1 < nT) loadTile((it + S_GU - 1) % S_GU, it + S_GU - 1);
        asm volatile("cp.async.commit_group;" ::: "memory");

        const int buf = it % S_GU;
        const uint32_t aBase = smem_u32(sm + buf * GU_STAGE_HALVES);
        const uint32_t gBase = aBase + A_HALVES * 2;
        const uint32_t uBase = gBase + B_HALVES * 2;

        #pragma unroll
        for (int ks = 0; ks < 2; ++ks) {
            const int kk = ks * 16;
            uint32_t af[2][4];
            #pragma unroll
            for (int mi = 0; mi < 2; ++mi) {
                int row = warpRow * 32 + mi * 16 + (lane & 15);
                int col = kk + ((lane >> 4) << 3);
                uint32_t addr = aBase + (uint32_t)((row * LDA + col) * 2);
                asm volatile(
                    "ldmatrix.sync.aligned.m8n8.x4.shared.b16 {%0,%1,%2,%3}, [%4];"
                    : "=r"(af[mi][0]), "=r"(af[mi][1]), "=r"(af[mi][2]), "=r"(af[mi][3])
                    : "r"(addr));
            }
            // gate
            {
                uint32_t bf[4][2];
                #pragma unroll
                for (int nj = 0; nj < 2; ++nj) {
                    int row = kk + (lane & 15);
                    int col = warpCol * 32 + nj * 16 + ((lane >> 4) << 3);
                    uint32_t addr = gBase + (uint32_t)((row * LDB + col) * 2);
                    uint32_t r0, r1, r2, r3;
                    asm volatile(
                        "ldmatrix.sync.aligned.m8n8.x4.trans.shared.b16 {%0,%1,%2,%3}, [%4];"
                        : "=r"(r0), "=r"(r1), "=r"(r2), "=r"(r3) : "r"(addr));
                    bf[nj * 2][0] = r0; bf[nj * 2][1] = r1;
                    bf[nj * 2 + 1][0] = r2; bf[nj * 2 + 1][1] = r3;
                }
                #pragma unroll
                for (int mi = 0; mi < 2; ++mi)
                    #pragma unroll
                    for (int ni = 0; ni < 4; ++ni) {
                        float* c = accg[mi][ni];
                        asm volatile(
                            "mma.sync.aligned.m16n8k16.row.col.f32.f16.f16.f32 "
                            "{%0,%1,%2,%3}, {%4,%5,%6,%7}, {%8,%9}, {%0,%1,%2,%3};"
                            : "+f"(c[0]), "+f"(c[1]), "+f"(c[2]), "+f"(c[3])
                            : "r"(af[mi][0]), "r"(af[mi][1]), "r"(af[mi][2]), "r"(af[mi][3]),
                              "r"(bf[ni][0]), "r"(bf[ni][1]));
                    }
            }
            // up
            {
                uint32_t bf[4][2];
                #pragma unroll
                for (int nj = 0; nj < 2; ++nj) {
                    int row = kk + (lane & 15);
                    int col = warpCol * 32 + nj * 16 + ((lane >> 4) << 3);
                    uint32_t addr = uBase + (uint32_t)((row * LDB + col) * 2);
                    uint32_t r0, r1, r2, r3;
                    asm volatile(
                        "ldmatrix.sync.aligned.m8n8.x4.trans.shared.b16 {%0,%1,%2,%3}, [%4];"
                        : "=r"(r0), "=r"(r1), "=r"(r2), "=r"(r3) : "r"(addr));
                    bf[nj * 2][0] = r0; bf[nj * 2][1] = r1;
                    bf[nj * 2 + 1][0] = r2; bf[nj * 2 + 1][1] = r3;
                }
                #pragma unroll
                for (int mi = 0; mi < 2; ++mi)
                    #pragma unroll
                    for (int ni = 0; ni < 4; ++ni) {
                        float* c = accu[mi][ni];
                        asm volatile(
                            "mma.sync.aligned.m16n8k16.row.col.f32.f16.f16.f32 "
                            "{%0,%1,%2,%3}, {%4,%5,%6,%7}, {%8,%9}, {%0,%1,%2,%3};"
                            : "+f"(c[0]), "+f"(c[1]), "+f"(c[2]), "+f"(c[3])
                            : "r"(af[mi][0]), "r"(af[mi][1]), "r"(af[mi][2]), "r"(af[mi][3]),
                              "r"(bf[ni][0]), "r"(bf[ni][1]));
                    }
            }
        }
    }

    // epilogue: h = silu(g) * u, fp16
    #pragma unroll
    for (int mi = 0; mi < 2; ++mi) {
        #pragma unroll
        for (int ni = 0; ni < 4; ++ni) {
            int row = mBase + warpRow * 32 + mi * 16 + (lane >> 2);
            int col = nBase + warpCol * 32 + ni * 8 + ((lane & 3) << 1);
            float g0 = accg[mi][ni][0], g1 = accg[mi][ni][1];
            float g2 = accg[mi][ni][2], g3 = accg[mi][ni][3];
            float s0 = g0 / (1.0f + __expf(-g0));
            float s1 = g1 / (1.0f + __expf(-g1));
            float s2 = g2 / (1.0f + __expf(-g2));
            float s3 = g3 / (1.0f + __expf(-g3));
            __half2 h01 = __floats2half2_rn(s0 * accu[mi][ni][0], s1 * accu[mi][ni][1]);
            __half2 h23 = __floats2half2_rn(s2 * accu[mi][ni][2], s3 * accu[mi][ni][3]);
            *reinterpret_cast<__half2*>(&H[(size_t)row * INTER + col]) = h01;
            *reinterpret_cast<__half2*>(&H[(size_t)(row + 8) * INTER + col]) = h23;
        }
    }

    __threadfence();
    __syncthreads();
    if (tid == 0) atomicAdd(&g_hcnt[by], 1);
}

// ================= down tile (occ 2, fp32 acc) =============================
__device__ void down_tile(__half* sm, int bx, int by,
                          const __half* __restrict__ A, const __half* __restrict__ B,
                          float* __restrict__ C)
{
    const int tid  = threadIdx.x;
    const int lane = tid & 31;
    const int warp = tid >> 5;
    const int warpRow = warp >> 1;   // 0..3
    const int warpCol = warp & 1;    // 0..1
    const int mBase = by * BM;
    const int nBase = bx * BN;

    // wait until all 88 gate+up tiles of this row block have published h
    if (tid == 0) {
        while (atomicAdd(&g_hcnt[by], 0) < 88) __nanosleep(64);
        __threadfence();
    }
    __syncthreads();

    float acc[2][4][4] = {};

    auto loadTile = [&](int buf, int kt) {
        const int k0 = kt * BK;
        __half* stA = sm + buf * DN_STAGE_HALVES;
        __half* stB = stA + A_HALVES;
        #pragma unroll
        for (int rep = 0; rep < 2; ++rep) {
            int i = tid + rep * 256;
            int r = i >> 2, c = i & 3;
            cp_async16(smem_u32(&stA[r * LDA + c * 8]),
                       A + (size_t)(mBase + r) * INTER + (k0 + c * 8));
        }
        {
            int r = tid >> 3, c = tid & 7;
            cp_async16(smem_u32(&stB[r * LDB + c * 8]),
                       B + (size_t)(k0 + r) * HIDDEN + (nBase + c * 8));
        }
    };

    const int nT = INTER / BK;   // 176
    #pragma unroll
    for (int s = 0; s < S_DN - 1; ++s) {
        loadTile(s, s);
        asm volatile("cp.async.commit_group;" ::: "memory");
    }

    for (int it = 0; it < nT; ++it) {
        asm volatile("cp.async.wait_group %0;" :: "n"(S_DN - 2) : "memory");
        __syncthreads();
        if (it + S_DN - 1 < nT) loadTile((it + S_DN - 1) % S_DN, it + S_DN - 1);
        asm volatile("cp.async.commit_group;" ::: "memory");

        const int buf = it % S_DN;
        const uint32_t aBase = smem_u32(sm + buf * DN_STAGE_HALVES);
        const uint32_t bBase = aBase + A_HALVES * 2;

        #pragma unroll
        for (int ks = 0; ks < 2; ++ks) {
            const int kk = ks * 16;
            uint32_t af[2][4];
            #pragma unroll
            for (int mi = 0; mi < 2; ++mi) {
                int row = warpRow * 32 + mi * 16 + (lane & 15);
                int col = kk + ((lane >> 4) << 3);
                uint32_t addr = aBase + (uint32_t)((row * LDA + col) * 2);
                asm volatile(
                    "ldmatrix.sync.aligned.m8n8.x4.shared.b16 {%0,%1,%2,%3}, [%4];"
                    : "=r"(af[mi][0]), "=r"(af[mi][1]), "=r"(af[mi][2]), "=r"(af[mi][3])
                    : "r"(addr));
            }
            uint32_t bf[4][2];
            #pragma unroll
            for (int nj = 0; nj < 2; ++nj) {
                int row = kk + (lane & 15);
                int col = warpCol * 32 + nj * 16 + ((lane >> 4) << 3);
                uint32_t addr = bBase + (uint32_t)((row * LDB + col) * 2);
                uint32_t r0, r1, r2, r3;
                asm volatile(
                    "ldmatrix.sync.aligned.m8n8.x4.trans.shared.b16 {%0,%1,%2,%3}, [%4];"
                    : "=r"(r0), "=r"(r1), "=r"(r2), "=r"(r3) : "r"(addr));
                bf[nj * 2][0] = r0; bf[nj * 2][1] = r1;
                bf[nj * 2 + 1][0] = r2; bf[nj * 2 + 1][1] = r3;
            }
            #pragma unroll
            for (int mi = 0; mi < 2; ++mi)
                #pragma unroll
                for (int ni = 0; ni < 4; ++ni) {
                    float* c = acc[mi][ni];
                    asm volatile(
                        "mma.sync.aligned.m16n8k16.row.col.f32.f16.f16.f32 "
                        "{%0,%1,%2,%3}, {%4,%5,%6,%7}, {%8,%9}, {%0,%1,%2,%3};"
                        : "+f"(c[0]), "+f"(c[1]), "+f"(c[2]), "+f"(c[3])
                        : "r"(af[mi][0]), "r"(af[mi][1]), "r"(af[mi][2]), "r"(af[mi][3]),
                          "r"(bf[ni][0]), "r"(bf[ni][1]));
                }
        }
    }

    #pragma unroll
    for (int mi = 0; mi < 2; ++mi) {
        #pragma unroll
        for (int ni = 0; ni < 4; ++ni) {
            int row = mBase + warpRow * 32 + mi * 16 + (lane >> 2);
            int col = nBase + warpCol * 32 + ni * 8 + ((lane & 3) << 1);
            float2* p0 = reinterpret_cast<float2*>(&C[(size_t)row * HIDDEN + col]);
            float2* p1 = reinterpret_cast<float2*>(&C[(size_t)(row + 8) * HIDDEN + col]);
            *p0 = make_float2(acc[mi][ni][0], acc[mi][ni][1]);
            *p1 = make_float2(acc[mi][ni][2], acc[mi][ni][3]);
        }
    }
}

// ================= merged GEMM kernel (occ 2) ==============================
__global__ void __launch_bounds__(256, 2)
gemm_merged_kernel(const __half* __restrict__ xh,
                   const __half* __restrict__ wg, const __half* __restrict__ wu,
                   __half* __restrict__ hh,
                   const __half* __restrict__ wd, float* __restrict__ out)
{
    extern __shared__ __half sm[];
    const int b = blockIdx.x;
    if (b < GU_TILES) {
        gateup_tile(sm, b % 88, b / 88, xh, wg, wu, hh);
    } else {
        int r = b - GU_TILES;
        down_tile(sm, r % 32, r / 32, hh, wd, out);
    }
}

// ---------------- launcher ----------------
extern "C" void kernel_launch(void* const* d_in, const int* in_sizes, int n_in,
                              void* d_out, int out_size) {
    (void)in_sizes; (void)n_in; (void)out_size;
    const float* x  = (const float*)d_in[0];
    const int*   gq = (const int*)  d_in[1];
    const int*   gz = (const int*)  d_in[2];
    const float* gs = (const float*)d_in[3];
    const int*   uq = (const int*)  d_in[4];
    const int*   uz = (const int*)  d_in[5];
    const float* us = (const float*)d_in[6];
    const int*   dq = (const int*)  d_in[7];
    const int*   dz = (const int*)  d_in[8];
    const float* ds = (const float*)d_in[9];

    void *wg, *wu, *wd, *xh, *hh;
    cudaGetSymbolAddress(&wg, g_wg);
    cudaGetSymbolAddress(&wu, g_wu);
    cudaGetSymbolAddress(&wd, g_wd);
    cudaGetSymbolAddress(&xh, g_x);
    cudaGetSymbolAddress(&hh, g_h);

    cudaFuncSetAttribute(gemm_merged_kernel,
                         cudaFuncAttributeMaxDynamicSharedMemorySize, GU_SMEM_BYTES);

    // 1) fused prep: x->fp16 + all three dequants + counter reset
    prep_kernel<<<PREP_BLKS, 256>>>(
        (const float4*)x,
        gq, gz, gs, uq, uz, us, dq, dz, ds,
        (__half*)wg, (__half*)wu, (__half*)wd, (uint2*)xh);

    // 2) merged GEMM (occ 2): gate+up tiles then down tiles (down backfills tail)
    gemm_merged_kernel<<<MERGED_BLKS, 256, GU_SMEM_BYTES>>>(
        (const __half*)xh, (const __half*)wg, (const __half*)wu,
        (__half*)hh, (const __half*)wd, (float*)d_out);
}